// round 14
// baseline (speedup 1.0000x reference)
#include <cuda_runtime.h>
#include <cuda_bf16.h>
#include <cstdint>

#define N 4096
#define D 128
#define HB1 256   // pass1 blocks
#define GB  528   // gemm blocks

#define TSTRIDE 272
#define TILE_B (128 * TSTRIDE)
#define T_AHI 0
#define T_ALO TILE_B
#define T_BHI (2 * TILE_B)
#define T_BLO (3 * TILE_B)
#define DYN_SMEM (4 * TILE_B)      // 139264

// ---------------- device globals (all accumulators have identity == 0) ----------------
__device__ __align__(16) __nv_bfloat16 g_ahi[N * D];
__device__ __align__(16) __nv_bfloat16 g_alo[N * D];
__device__ float g_tsorted[N];
__device__ unsigned char g_low[N];
__device__ unsigned g_rowMinInv[N];
__device__ unsigned g_rowMaxNeg[N];
__device__ unsigned g_hist1[4096];
__device__ unsigned g_hist2[4096];
__device__ unsigned g_hist20[1 << 20];
__device__ unsigned g_zeroPairs;
__device__ unsigned g_doneCtr[4];
__device__ unsigned g_p1, g_r1, g_mLo, g_mHi;
__device__ float    g_frac;
__device__ unsigned g_minCrossInv;
__device__ float    g_actT;

__device__ __forceinline__ unsigned encodeF(float f) {
    unsigned u = __float_as_uint(f);
    return (u & 0x80000000u) ? ~u : (u | 0x80000000u);
}
__device__ __forceinline__ float decodeF(unsigned u) {
    return (u & 0x80000000u) ? __uint_as_float(u & 0x7FFFFFFFu)
                             : __uint_as_float(~u);
}

__device__ __forceinline__ void rankMath(unsigned z, unsigned& mLo, unsigned& mHi, float& frac) {
    unsigned long long n = 16773120ull - 2ull * (unsigned long long)z;
    float nf = (float)(n - 1ull);
    float pos = 0.2f * nf;
    float lof = floorf(pos);
    frac = pos - lof;
    unsigned fl = (unsigned)lof;
    mLo = fl >> 1;
    mHi = (fl + 1u) >> 1;
}

__device__ __forceinline__ uint32_t smem_u32(const void* p) {
    uint32_t a;
    asm("{ .reg .u64 tmp; cvta.to.shared.u64 tmp, %1; cvt.u32.u64 %0, tmp; }" : "=r"(a) : "l"(p));
    return a;
}
__device__ __forceinline__ void ldsm4(unsigned* r, unsigned addr) {
    asm volatile("ldmatrix.sync.aligned.m8n8.x4.shared.b16 {%0,%1,%2,%3}, [%4];"
                 : "=r"(r[0]), "=r"(r[1]), "=r"(r[2]), "=r"(r[3]) : "r"(addr));
}
__device__ __forceinline__ void mma16816(float* d, const unsigned* a, unsigned b0, unsigned b1) {
    asm volatile("mma.sync.aligned.m16n8k16.row.col.f32.bf16.bf16.f32 "
                 "{%0,%1,%2,%3}, {%4,%5,%6,%7}, {%8,%9}, {%0,%1,%2,%3};"
                 : "+f"(d[0]), "+f"(d[1]), "+f"(d[2]), "+f"(d[3])
                 : "r"(a[0]), "r"(a[1]), "r"(a[2]), "r"(a[3]), "r"(b0), "r"(b1));
}

// ---- locate helpers: 512-thread block variants (8 bins/thread, 16 warps) ----
__device__ void locateS4096_512(const unsigned* h, unsigned rank, volatile unsigned* wS,
                                volatile unsigned* outBin, volatile unsigned* outRem) {
    int tid = threadIdx.x, lane = tid & 31, wid = tid >> 5;
    unsigned hl[8], lsum = 0;
#pragma unroll
    for (int k = 0; k < 8; k++) { hl[k] = h[tid * 8 + k]; lsum += hl[k]; }
    unsigned v = lsum;
#pragma unroll
    for (int s = 1; s < 32; s <<= 1) {
        unsigned o = __shfl_up_sync(0xffffffffu, v, s);
        if (lane >= s) v += o;
    }
    if (lane == 31) wS[wid] = v;
    __syncthreads();
    if (tid == 0) { unsigned run = 0; for (int w = 0; w < 16; w++) { run += wS[w]; wS[w] = run; } }
    __syncthreads();
    unsigned cum = (v - lsum) + (wid ? wS[wid - 1] : 0u);
#pragma unroll
    for (int k = 0; k < 8; k++) {
        unsigned hh = hl[k];
        if (hh && rank >= cum && rank < cum + hh) { *outBin = (unsigned)(tid * 8 + k); *outRem = rank - cum; }
        cum += hh;
    }
    __syncthreads();
}
__device__ void locateG4096_512(const unsigned* gh, unsigned rank, volatile unsigned* wS,
                                volatile unsigned* outBin, volatile unsigned* outRem) {
    int tid = threadIdx.x, lane = tid & 31, wid = tid >> 5;
    unsigned hl[8], lsum = 0;
#pragma unroll
    for (int k = 0; k < 8; k++) { hl[k] = __ldcg(&gh[tid * 8 + k]); lsum += hl[k]; }
    unsigned v = lsum;
#pragma unroll
    for (int s = 1; s < 32; s <<= 1) {
        unsigned o = __shfl_up_sync(0xffffffffu, v, s);
        if (lane >= s) v += o;
    }
    if (lane == 31) wS[wid] = v;
    __syncthreads();
    if (tid == 0) { unsigned run = 0; for (int w = 0; w < 16; w++) { run += wS[w]; wS[w] = run; } }
    __syncthreads();
    unsigned cum = (v - lsum) + (wid ? wS[wid - 1] : 0u);
#pragma unroll
    for (int k = 0; k < 8; k++) {
        unsigned hh = hl[k];
        if (hh && rank >= cum && rank < cum + hh) { *outBin = (unsigned)(tid * 8 + k); *outRem = rank - cum; }
        cum += hh;
    }
    __syncthreads();
}
// ---- 256-thread variants (for selK) ----
__device__ void locateG4096(const unsigned* gh, unsigned rank, volatile unsigned* wS,
                            volatile unsigned* outBin, volatile unsigned* outRem) {
    int tid = threadIdx.x, lane = tid & 31, wid = tid >> 5;
    unsigned hl[16], lsum = 0;
#pragma unroll
    for (int k = 0; k < 16; k++) { hl[k] = __ldcg(&gh[tid * 16 + k]); lsum += hl[k]; }
    unsigned v = lsum;
#pragma unroll
    for (int s = 1; s < 32; s <<= 1) {
        unsigned o = __shfl_up_sync(0xffffffffu, v, s);
        if (lane >= s) v += o;
    }
    if (lane == 31) wS[wid] = v;
    __syncthreads();
    if (tid == 0) { unsigned run = 0; for (int w = 0; w < 8; w++) { run += wS[w]; wS[w] = run; } }
    __syncthreads();
    unsigned cum = (v - lsum) + (wid ? wS[wid - 1] : 0u);
#pragma unroll
    for (int k = 0; k < 16; k++) {
        unsigned h = hl[k];
        if (h && rank >= cum && rank < cum + h) { *outBin = (unsigned)(tid * 16 + k); *outRem = rank - cum; }
        cum += h;
    }
    __syncthreads();
}
__device__ void locateG256(const unsigned* gh, unsigned rank, volatile unsigned* wS,
                           volatile unsigned* outBin, volatile unsigned* outRem,
                           volatile unsigned* outCnt) {
    int tid = threadIdx.x, lane = tid & 31, wid = tid >> 5;
    unsigned h = __ldcg(&gh[tid]);
    unsigned v = h;
#pragma unroll
    for (int s = 1; s < 32; s <<= 1) {
        unsigned o = __shfl_up_sync(0xffffffffu, v, s);
        if (lane >= s) v += o;
    }
    if (lane == 31) wS[wid] = v;
    __syncthreads();
    if (tid == 0) { unsigned run = 0; for (int w = 0; w < 8; w++) { run += wS[w]; wS[w] = run; } }
    __syncthreads();
    unsigned cum = (v - h) + (wid ? wS[wid - 1] : 0u);
    if (h && rank >= cum && rank < cum + h) { *outBin = (unsigned)tid; *outRem = rank - cum; *outCnt = h; }
    __syncthreads();
}

// ================ K1 (512 thr): [pass1: 0-255] [norm+zero20: 256-319] [median: 320] [sort: 321] ================
__global__ __launch_bounds__(512) void prepPass1K(const float* __restrict__ t,
                                                  const float* __restrict__ emb,
                                                  const float* __restrict__ au) {
    __shared__ __align__(16) unsigned char sbuf[32768];
    __shared__ unsigned wS[16];
    __shared__ unsigned sA, sB_;
    __shared__ unsigned sAgg;
    __shared__ int sLast;
    int tid = threadIdx.x;
    int bid = blockIdx.x;

    if (bid < HB1) {
        // ---- pass 1: 12-bit smem histogram + tie count ----
        float4* tsv4 = (float4*)sbuf;
        unsigned* hist = (unsigned*)(sbuf + 16384);
        const float* tss = (const float*)tsv4;
        for (int k = tid; k < 1024; k += 512) tsv4[k] = ((const float4*)t)[k];
        for (int x = tid; x < 4096; x += 512) hist[x] = 0u;
        if (tid == 0) sAgg = 0u;
        __syncthreads();

        unsigned zc = 0u;
        for (int i = bid; i < N; i += HB1) {
            float ti = tss[i];
            int v0 = (i + 1) >> 2;
            for (int v = v0 + tid; v < 1024; v += 512) {
                float4 w = tsv4[v];
                int jb = v << 2;
#pragma unroll
                for (int k = 0; k < 4; k++) {
                    float tj = (k == 0) ? w.x : (k == 1) ? w.y : (k == 2) ? w.z : w.w;
                    if (jb + k > i) {
                        unsigned b = __float_as_uint(fabsf(ti - tj));
                        if (b == 0u) zc++;
                        else atomicAdd(&hist[b >> 20], 1u);
                    }
                }
            }
        }
        __syncthreads();
        for (int x = tid; x < 4096; x += 512)
            if (hist[x]) atomicAdd(&g_hist1[x], hist[x]);
#pragma unroll
        for (int s = 16; s > 0; s >>= 1) zc += __shfl_xor_sync(0xffffffffu, zc, s);
        if ((tid & 31) == 0 && zc) atomicAdd(&sAgg, zc);
        __syncthreads();
        if (tid == 0 && sAgg) atomicAdd(&g_zeroPairs, sAgg);

        __threadfence();
        if (tid == 0) sLast = (atomicAdd(&g_doneCtr[0], 1u) == (unsigned)(HB1 - 1)) ? 1 : 0;
        __syncthreads();
        if (!sLast) return;

        unsigned z = __ldcg(&g_zeroPairs);
        unsigned mLo, mHi; float frac;
        rankMath(z, mLo, mHi, frac);
        locateG4096_512(g_hist1, mLo, wS, &sA, &sB_);
        if (tid == 0) {
            g_p1 = sA; g_r1 = sB_;
            g_mLo = mLo; g_mHi = mHi; g_frac = frac;
        }
        return;
    }

    if (bid < HB1 + 64) {
        // ---- normalize 64 rows -> bf16 hi/lo + zero hist20 slice ----
        int nb = bid - HB1;
        for (int x = tid; x < 16384; x += 512) g_hist20[nb * 16384 + x] = 0u;
        int warp = tid >> 5, lane = tid & 31;
#pragma unroll
        for (int q = 0; q < 4; q++) {
            int row = nb * 64 + warp * 4 + q;
            const float4* p = (const float4*)(emb + (size_t)row * D);
            float4 v = p[lane];
            float ss = v.x * v.x + v.y * v.y + v.z * v.z + v.w * v.w;
#pragma unroll
            for (int st = 16; st > 0; st >>= 1) ss += __shfl_xor_sync(0xffffffffu, ss, st);
            float inv = 1.0f / fmaxf(sqrtf(ss), 1e-12f);
            float o[4] = {v.x * inv, v.y * inv, v.z * inv, v.w * inv};
            __nv_bfloat16 h[4], l[4];
#pragma unroll
            for (int u = 0; u < 4; u++) {
                h[u] = __float2bfloat16(o[u]);
                l[u] = __float2bfloat16(o[u] - __bfloat162float(h[u]));
            }
            __nv_bfloat162* ph = (__nv_bfloat162*)(g_ahi + (size_t)row * D);
            __nv_bfloat162* pl = (__nv_bfloat162*)(g_alo + (size_t)row * D);
            ph[lane * 2]     = __nv_bfloat162{h[0], h[1]};
            ph[lane * 2 + 1] = __nv_bfloat162{h[2], h[3]};
            pl[lane * 2]     = __nv_bfloat162{l[0], l[1]};
            pl[lane * 2 + 1] = __nv_bfloat162{l[2], l[3]};
        }
        return;
    }

    if (bid == HB1 + 64) {
        // ---- median of au via 3-level radix select (ranks 2047, 2048) ----
        unsigned* e = (unsigned*)sbuf;
        unsigned* h = (unsigned*)(sbuf + 16384);
        for (int i = tid; i < N; i += 512) e[i] = encodeF(au[i]);
        __syncthreads();
        float vals[2];
#pragma unroll 1
        for (int r = 0; r < 2; r++) {
            unsigned rank = 2047u + (unsigned)r;
            for (int x = tid; x < 4096; x += 512) h[x] = 0u;
            __syncthreads();
            for (int i = tid; i < N; i += 512) atomicAdd(&h[e[i] >> 20], 1u);
            __syncthreads();
            locateS4096_512(h, rank, wS, &sA, &sB_);
            unsigned b1 = sA, r1 = sB_;
            __syncthreads();
            for (int x = tid; x < 4096; x += 512) h[x] = 0u;
            __syncthreads();
            for (int i = tid; i < N; i += 512)
                if ((e[i] >> 20) == b1) atomicAdd(&h[(e[i] >> 8) & 0xFFFu], 1u);
            __syncthreads();
            locateS4096_512(h, r1, wS, &sA, &sB_);
            unsigned b2 = sA, r2 = sB_;
            unsigned pfx = (b1 << 12) | b2;
            __syncthreads();
            for (int x = tid; x < 4096; x += 512) h[x] = 0u;
            __syncthreads();
            for (int i = tid; i < N; i += 512)
                if ((e[i] >> 8) == pfx) atomicAdd(&h[e[i] & 0xFFu], 1u);
            __syncthreads();
            locateS4096_512(h, r2, wS, &sA, &sB_);
            unsigned b3 = sA;
            __syncthreads();
            vals[r] = decodeF((b1 << 20) | (b2 << 8) | b3);
        }
        float th = __fadd_rn(__fmul_rn(vals[0], 0.5f), __fmul_rn(vals[1], 0.5f));
        for (int i = tid; i < N; i += 512) g_low[i] = (au[i] < th) ? 1 : 0;
        return;
    }

    // ---- sort targets (bitonic, 512 threads) ----
    {
        float* s = (float*)sbuf;
        for (int i = tid; i < N; i += 512) s[i] = t[i];
        __syncthreads();
        for (int k = 2; k <= N; k <<= 1) {
            for (int j = k >> 1; j > 0; j >>= 1) {
                for (int idx = tid; idx < N; idx += 512) {
                    int p = idx ^ j;
                    if (p > idx) {
                        float a = s[idx], b2 = s[p];
                        bool up = ((idx & k) == 0);
                        bool sw = up ? (a > b2) : (a < b2);
                        if (sw) { s[idx] = b2; s[p] = a; }
                    }
                }
                __syncthreads();
            }
        }
        for (int i = tid; i < N; i += 512) g_tsorted[i] = s[i];
    }
}

// ================ K2: windowed pass 2 over sorted targets (no pair scan) ================
__global__ __launch_bounds__(256) void winPass2K() {
    __shared__ float ts[N];
    int tid = threadIdx.x;
    int warp = tid >> 5, lane = tid & 31;
    for (int i = tid; i < N; i += 256) ts[i] = g_tsorted[i];
    unsigned p1 = g_p1;
    unsigned loB = p1 << 20;
    unsigned hiB = ((p1 + 1u) << 20) - 1u;
    float loV = __uint_as_float(loB);
    float hiV = __uint_as_float(hiB);
    __syncthreads();

    int wg = blockIdx.x * 8 + warp;   // 1024 warps cover rows strided
    for (int i = wg; i < N; i += 1024) {
        float ti = ts[i];
        // jlo: first j>i with ts[j]-ti >= loV (all if loB==0)
        int jlo;
        if (loB == 0u) jlo = i + 1;
        else {
            int lo = i + 1, hi = N;
            while (lo < hi) {
                int m = (lo + hi) >> 1;
                if (ts[m] - ti >= loV) hi = m; else lo = m + 1;
            }
            jlo = lo;
        }
        // jhiEx: first j >= jlo with ts[j]-ti > hiV
        int lo = jlo, hi = N;
        while (lo < hi) {
            int m = (lo + hi) >> 1;
            if (ts[m] - ti > hiV) hi = m; else lo = m + 1;
        }
        int jhiEx = lo;
        // enumerate window pairs -> global hist2 / hist20
        for (int j = jlo + lane; j < jhiEx; j += 32) {
            unsigned b = __float_as_uint(ts[j] - ti);
            if (b != 0u) {
                atomicAdd(&g_hist2[(b >> 8) & 0xFFFu], 1u);
                atomicAdd(&g_hist20[b & 0xFFFFFu], 1u);
            }
        }
        // cross-bin min (first diff beyond the window)
        if (lane == 0 && jhiEx < N) {
            unsigned c = __float_as_uint(ts[jhiEx] - ti);
            atomicMax(&g_minCrossInv, ~c);
        }
    }
}

// ================ K3: selection -> g_actT (1 block, 256 threads) ================
__global__ __launch_bounds__(256) void selK() {
    __shared__ unsigned wS[8];
    __shared__ unsigned sA, sB_, sC_, sD_;
    int tid = threadIdx.x;
    unsigned p1 = g_p1;
    unsigned r1 = g_r1;
    locateG4096(g_hist2, r1, wS, &sA, &sB_);
    unsigned bin2 = sA, rem2 = sB_;
    __syncthreads();
    locateG256(&g_hist20[bin2 << 8], rem2, wS, &sA, &sB_, &sC_);
    unsigned bin3 = sA, rem3 = sB_, cnt3 = sC_;
    __syncthreads();
    if (tid == 0) { sA = 0xFFFFFFFFu; sB_ = 0xFFFFFFFFu; sD_ = 0xFFFFFFFFu; }
    __syncthreads();
    if ((unsigned)tid > bin3 && __ldcg(&g_hist20[(bin2 << 8) + tid]) != 0u)
        atomicMin(&sA, (unsigned)tid);
#pragma unroll
    for (int k = 0; k < 16; k++) {
        unsigned idx = (unsigned)tid * 16u + (unsigned)k;
        if (idx > bin2 && __ldcg(&g_hist2[idx]) != 0u) atomicMin(&sB_, idx);
    }
    __syncthreads();
    unsigned nextA = sA, nbin2 = sB_;
    if (nbin2 != 0xFFFFFFFFu) {
        if (__ldcg(&g_hist20[(nbin2 << 8) + tid]) != 0u) atomicMin(&sD_, (unsigned)tid);
    }
    __syncthreads();
    if (tid == 0) {
        unsigned vlo = (p1 << 20) | (bin2 << 8) | bin3;
        unsigned mLo = g_mLo, mHi = g_mHi;
        float frac = g_frac;
        unsigned mAb = 0xFFFFFFFFu;
        if (nextA != 0xFFFFFFFFu) mAb = min(mAb, (p1 << 20) | (bin2 << 8) | nextA);
        if (nbin2 != 0xFFFFFFFFu && sD_ != 0xFFFFFFFFu)
            mAb = min(mAb, (p1 << 20) | (nbin2 << 8) | sD_);
        unsigned crossInv = __ldcg(&g_minCrossInv);
        if (crossInv) mAb = min(mAb, ~crossInv);
        bool same = (mHi == mLo) || (rem3 + 1u < cnt3);
        float flo = __uint_as_float(vlo);
        float fhi = same ? flo : __uint_as_float(mAb);
        g_actT = __fadd_rn(__fmul_rn(flo, 1.0f - frac), __fmul_rn(fhi, frac));
    }
}

// ================ K4: HMMA bf16-split GEMM + masked epilogue; last block: final + resets ================
extern __shared__ unsigned char g_dyn[];
__global__ __launch_bounds__(256) void gemmHK(const float* __restrict__ t,
                                              float* __restrict__ out, int out_size) {
    __shared__ float tCol[128];
    __shared__ unsigned char lowCol[128];
    __shared__ unsigned sColMinI[4][128];
    __shared__ unsigned sColMax[4][128];
    __shared__ float fred[8];
    __shared__ unsigned ured[8];
    __shared__ int sLast;

    int tid = threadIdx.x;     // 256
    int warp = tid >> 5, lane = tid & 31;

    int b = blockIdx.x;
    int bi = 0;
    while (b >= 32 - bi) { b -= 32 - bi; bi++; }
    int bj = bi + b;
    int ri = bi * 128, rj = bj * 128;

    uint32_t sbase = smem_u32(g_dyn);

    for (int i = tid; i < 2048; i += 256) {
        int row = i >> 4, ch = i & 15;
        unsigned off = (unsigned)row * TSTRIDE + (unsigned)ch * 16u;
        *(uint4*)(g_dyn + T_AHI + off) = ((const uint4*)(g_ahi + (size_t)(ri + row) * D))[ch];
        *(uint4*)(g_dyn + T_ALO + off) = ((const uint4*)(g_alo + (size_t)(ri + row) * D))[ch];
        *(uint4*)(g_dyn + T_BHI + off) = ((const uint4*)(g_ahi + (size_t)(rj + row) * D))[ch];
        *(uint4*)(g_dyn + T_BLO + off) = ((const uint4*)(g_alo + (size_t)(rj + row) * D))[ch];
    }
    if (tid < 128) {
        tCol[tid] = t[rj + tid];
        lowCol[tid] = g_low[rj + tid];
    }
    __syncthreads();

    int wr = warp >> 1, wc = warp & 1;
    int R = wr * 32, C = wc * 64;

    float acc[2][8][4];
#pragma unroll
    for (int mt = 0; mt < 2; mt++)
#pragma unroll
        for (int nt = 0; nt < 8; nt++)
#pragma unroll
            for (int q = 0; q < 4; q++) acc[mt][nt][q] = 0.0f;

    unsigned aRow = (unsigned)((lane & 7) + ((lane >> 3) & 1) * 8);
    unsigned aByte = (unsigned)((lane >> 4) * 16);
    unsigned bRow = (unsigned)(((lane >> 4) * 8) + (lane & 7));
    unsigned bByte = (unsigned)(((lane >> 3) & 1) * 16);

#pragma unroll 1
    for (int split = 0; split < 3; split++) {
        unsigned At = sbase + ((split == 2) ? T_ALO : T_AHI);
        unsigned Bt = sbase + ((split == 1) ? T_BLO : T_BHI);
#pragma unroll
        for (int kb = 0; kb < 8; kb++) {
            unsigned kByte = (unsigned)kb * 32u;
            unsigned a[2][4];
#pragma unroll
            for (int mt = 0; mt < 2; mt++) {
                unsigned addr = At + (unsigned)(R + mt * 16 + aRow) * TSTRIDE + kByte + aByte;
                ldsm4(a[mt], addr);
            }
#pragma unroll
            for (int ntp = 0; ntp < 4; ntp++) {
                unsigned bm[4];
                unsigned addr = Bt + (unsigned)(C + ntp * 16 + bRow) * TSTRIDE + kByte + bByte;
                ldsm4(bm, addr);
                mma16816(acc[0][ntp * 2],     a[0], bm[0], bm[1]);
                mma16816(acc[0][ntp * 2 + 1], a[0], bm[2], bm[3]);
                mma16816(acc[1][ntp * 2],     a[1], bm[0], bm[1]);
                mma16816(acc[1][ntp * 2 + 1], a[1], bm[2], bm[3]);
            }
        }
    }

    float actT = g_actT;
    float pMin[4], nMax[4];
#pragma unroll
    for (int u = 0; u < 4; u++) { pMin[u] = 3.402823466e38f; nMax[u] = -3.402823466e38f; }
    unsigned cMinI[8][2], cMax[8][2];
#pragma unroll
    for (int nt = 0; nt < 8; nt++) { cMinI[nt][0] = cMinI[nt][1] = 0u; cMax[nt][0] = cMax[nt][1] = 0u; }

#pragma unroll
    for (int mt = 0; mt < 2; mt++) {
        int rA = ri + R + mt * 16 + (lane >> 2);
        int rB = rA + 8;
        float tA = t[rA], tB = t[rB];
        int lA = g_low[rA], lB = g_low[rB];
#pragma unroll
        for (int nt = 0; nt < 8; nt++) {
            int lc0 = C + nt * 8 + (lane & 3) * 2;
#pragma unroll
            for (int s = 0; s < 2; s++) {
                int lc = lc0 + s;
                int gcol = rj + lc;
                float tc = tCol[lc];
                int lj = lowCol[lc];
                {
                    float dv = acc[mt][nt][s];
                    float ad = fabsf(tA - tc);
                    if (ad < actT) {
                        bool neq = rA != gcol;
                        if (lj) { if (neq) pMin[mt * 2] = fminf(pMin[mt * 2], dv); }
                        else nMax[mt * 2] = fmaxf(nMax[mt * 2], dv);
                        if (lA && neq) cMinI[nt][s] = max(cMinI[nt][s], ~encodeF(dv));
                        if (!lA) cMax[nt][s] = max(cMax[nt][s], encodeF(dv));
                    }
                }
                {
                    float dv = acc[mt][nt][2 + s];
                    float ad = fabsf(tB - tc);
                    if (ad < actT) {
                        bool neq = rB != gcol;
                        if (lj) { if (neq) pMin[mt * 2 + 1] = fminf(pMin[mt * 2 + 1], dv); }
                        else nMax[mt * 2 + 1] = fmaxf(nMax[mt * 2 + 1], dv);
                        if (lB && neq) cMinI[nt][s] = max(cMinI[nt][s], ~encodeF(dv));
                        if (!lB) cMax[nt][s] = max(cMax[nt][s], encodeF(dv));
                    }
                }
            }
        }
    }
#pragma unroll
    for (int s = 1; s < 4; s <<= 1) {
#pragma unroll
        for (int u = 0; u < 4; u++) {
            pMin[u] = fminf(pMin[u], __shfl_xor_sync(0xffffffffu, pMin[u], s));
            nMax[u] = fmaxf(nMax[u], __shfl_xor_sync(0xffffffffu, nMax[u], s));
        }
    }
    if ((lane & 3) == 0) {
#pragma unroll
        for (int mt = 0; mt < 2; mt++) {
            int rA = ri + R + mt * 16 + (lane >> 2);
            int rB = rA + 8;
            if (pMin[mt * 2] < 3.0e38f) atomicMax(&g_rowMinInv[rA], ~encodeF(pMin[mt * 2]));
            if (nMax[mt * 2] > -3.0e38f) atomicMax(&g_rowMaxNeg[rA], encodeF(nMax[mt * 2]));
            if (pMin[mt * 2 + 1] < 3.0e38f) atomicMax(&g_rowMinInv[rB], ~encodeF(pMin[mt * 2 + 1]));
            if (nMax[mt * 2 + 1] > -3.0e38f) atomicMax(&g_rowMaxNeg[rB], encodeF(nMax[mt * 2 + 1]));
        }
    }
#pragma unroll
    for (int s = 4; s < 32; s <<= 1) {
#pragma unroll
        for (int nt = 0; nt < 8; nt++)
#pragma unroll
            for (int q = 0; q < 2; q++) {
                cMinI[nt][q] = max(cMinI[nt][q], __shfl_xor_sync(0xffffffffu, cMinI[nt][q], s));
                cMax[nt][q] = max(cMax[nt][q], __shfl_xor_sync(0xffffffffu, cMax[nt][q], s));
            }
    }
    if (lane < 4) {
#pragma unroll
        for (int nt = 0; nt < 8; nt++)
#pragma unroll
            for (int q = 0; q < 2; q++) {
                int lc = C + nt * 8 + lane * 2 + q;
                sColMinI[wr][lc] = cMinI[nt][q];
                sColMax[wr][lc] = cMax[nt][q];
            }
    }
    __syncthreads();
    if (tid < 128) {
        unsigned vI = sColMinI[0][tid], vX = sColMax[0][tid];
#pragma unroll
        for (int w = 1; w < 4; w++) {
            vI = max(vI, sColMinI[w][tid]);
            vX = max(vX, sColMax[w][tid]);
        }
        if (vI) atomicMax(&g_rowMinInv[rj + tid], vI);
        if (vX) atomicMax(&g_rowMaxNeg[rj + tid], vX);
    }

    __threadfence();
    if (tid == 0) sLast = (atomicAdd(&g_doneCtr[2], 1u) == (unsigned)(GB - 1)) ? 1 : 0;
    __syncthreads();
    if (!sLast) return;

    float sum = 0.0f;
    unsigned cnt = 0u;
    for (int i = tid; i < N; i += 256) {
        if (g_low[i] == 0) continue;
        unsigned rInv = __ldcg(&g_rowMinInv[i]);
        if (rInv == 0u) continue;
        unsigned en = __ldcg(&g_rowMaxNeg[i]);
        if (en == 0u) continue;
        float minDot = decodeF(~rInv);
        float maxDot = decodeF(en);
        float hp = sqrtf(fmaxf(2.0f - 2.0f * minDot, 1e-12f));
        float hn = sqrtf(fmaxf(2.0f - 2.0f * maxDot, 1e-12f));
        float tl = hp - hn + 0.5f;
        if (tl < 0.0f) tl = 0.0f;
        sum += tl;
        cnt++;
    }
#pragma unroll
    for (int s = 16; s > 0; s >>= 1) {
        sum += __shfl_down_sync(0xffffffffu, sum, s);
        cnt += __shfl_down_sync(0xffffffffu, cnt, s);
    }
    if (lane == 0) { fred[warp] = sum; ured[warp] = cnt; }
    __syncthreads();
    if (tid == 0) {
        float s2 = 0.0f;
        unsigned c2 = 0u;
#pragma unroll
        for (int w = 0; w < 8; w++) { s2 += fred[w]; c2 += ured[w]; }
        out[0] = s2 / (float)(c2 > 0u ? c2 : 1u);
    }
    for (int i = tid; i < out_size; i += 256)
        if (i > 0) out[i] = 0.0f;

    for (int x = tid; x < 4096; x += 256) {
        g_hist1[x] = 0u;
        g_hist2[x] = 0u;
        g_rowMinInv[x] = 0u;
        g_rowMaxNeg[x] = 0u;
    }
    if (tid < 4) g_doneCtr[tid] = 0u;
    if (tid == 0) {
        g_zeroPairs = 0u;
        g_minCrossInv = 0u;
    }
}

// ---------------- launch ----------------
extern "C" void kernel_launch(void* const* d_in, const int* in_sizes, int n_in,
                              void* d_out, int out_size) {
    const float* emb = (const float*)d_in[0];
    const float* tg = (const float*)d_in[1];
    const float* au = (const float*)d_in[2];
    float* out = (float*)d_out;

    cudaFuncSetAttribute(gemmHK, cudaFuncAttributeMaxDynamicSharedMemorySize, DYN_SMEM);

    prepPass1K<<<HB1 + 64 + 2, 512>>>(tg, emb, au);     // 1
    winPass2K<<<128, 256>>>();                          // 2
    selK<<<1, 256>>>();                                 // 3
    gemmHK<<<GB, 256, DYN_SMEM>>>(tg, out, out_size);   // 4  (ncu capture slot)
}

// round 15
// speedup vs baseline: 1.0148x; 1.0148x over previous
#include <cuda_runtime.h>
#include <cuda_bf16.h>
#include <cstdint>

#define N 4096
#define D 128
#define HB1 256    // pass1 blocks
#define GB2 1056   // gemm blocks (64x128 tiles, bi <= 2*bj+1)

#define TSTRIDE 272
#define AT_B (64 * TSTRIDE)        // 17408
#define BT_B (128 * TSTRIDE)       // 34816
#define T_AHI 0
#define T_ALO AT_B
#define T_BHI (2 * AT_B)
#define T_BLO (2 * AT_B + BT_B)
#define DYN_SMEM (2 * AT_B + 2 * BT_B)   // 104448 -> 2 CTAs/SM

// ---------------- device globals (all accumulators have identity == 0) ----------------
__device__ __align__(16) __nv_bfloat16 g_ahi[N * D];
__device__ __align__(16) __nv_bfloat16 g_alo[N * D];
__device__ float g_tsorted[N];
__device__ unsigned char g_low[N];
__device__ unsigned g_rowMinInv[N];
__device__ unsigned g_rowMaxNeg[N];
__device__ unsigned g_hist1[4096];
__device__ unsigned g_hist2[4096];
__device__ unsigned g_hist20[1 << 20];
__device__ unsigned g_zeroPairs;
__device__ unsigned g_doneCtr[4];
__device__ unsigned g_p1, g_r1, g_mLo, g_mHi;
__device__ float    g_frac;
__device__ unsigned g_minCrossInv;
__device__ float    g_actT;

__device__ __forceinline__ unsigned encodeF(float f) {
    unsigned u = __float_as_uint(f);
    return (u & 0x80000000u) ? ~u : (u | 0x80000000u);
}
__device__ __forceinline__ float decodeF(unsigned u) {
    return (u & 0x80000000u) ? __uint_as_float(u & 0x7FFFFFFFu)
                             : __uint_as_float(~u);
}

__device__ __forceinline__ void rankMath(unsigned z, unsigned& mLo, unsigned& mHi, float& frac) {
    unsigned long long n = 16773120ull - 2ull * (unsigned long long)z;
    float nf = (float)(n - 1ull);
    float pos = 0.2f * nf;
    float lof = floorf(pos);
    frac = pos - lof;
    unsigned fl = (unsigned)lof;
    mLo = fl >> 1;
    mHi = (fl + 1u) >> 1;
}

__device__ __forceinline__ uint32_t smem_u32(const void* p) {
    uint32_t a;
    asm("{ .reg .u64 tmp; cvta.to.shared.u64 tmp, %1; cvt.u32.u64 %0, tmp; }" : "=r"(a) : "l"(p));
    return a;
}
__device__ __forceinline__ void ldsm4(unsigned* r, unsigned addr) {
    asm volatile("ldmatrix.sync.aligned.m8n8.x4.shared.b16 {%0,%1,%2,%3}, [%4];"
                 : "=r"(r[0]), "=r"(r[1]), "=r"(r[2]), "=r"(r[3]) : "r"(addr));
}
__device__ __forceinline__ void mma16816(float* d, const unsigned* a, unsigned b0, unsigned b1) {
    asm volatile("mma.sync.aligned.m16n8k16.row.col.f32.bf16.bf16.f32 "
                 "{%0,%1,%2,%3}, {%4,%5,%6,%7}, {%8,%9}, {%0,%1,%2,%3};"
                 : "+f"(d[0]), "+f"(d[1]), "+f"(d[2]), "+f"(d[3])
                 : "r"(a[0]), "r"(a[1]), "r"(a[2]), "r"(a[3]), "r"(b0), "r"(b1));
}

// ---- locate helpers ----
__device__ void locateS4096_512(const unsigned* h, unsigned rank, volatile unsigned* wS,
                                volatile unsigned* outBin, volatile unsigned* outRem) {
    int tid = threadIdx.x, lane = tid & 31, wid = tid >> 5;
    unsigned hl[8], lsum = 0;
#pragma unroll
    for (int k = 0; k < 8; k++) { hl[k] = h[tid * 8 + k]; lsum += hl[k]; }
    unsigned v = lsum;
#pragma unroll
    for (int s = 1; s < 32; s <<= 1) {
        unsigned o = __shfl_up_sync(0xffffffffu, v, s);
        if (lane >= s) v += o;
    }
    if (lane == 31) wS[wid] = v;
    __syncthreads();
    if (tid == 0) { unsigned run = 0; for (int w = 0; w < 16; w++) { run += wS[w]; wS[w] = run; } }
    __syncthreads();
    unsigned cum = (v - lsum) + (wid ? wS[wid - 1] : 0u);
#pragma unroll
    for (int k = 0; k < 8; k++) {
        unsigned hh = hl[k];
        if (hh && rank >= cum && rank < cum + hh) { *outBin = (unsigned)(tid * 8 + k); *outRem = rank - cum; }
        cum += hh;
    }
    __syncthreads();
}
__device__ void locateG4096_512(const unsigned* gh, unsigned rank, volatile unsigned* wS,
                                volatile unsigned* outBin, volatile unsigned* outRem) {
    int tid = threadIdx.x, lane = tid & 31, wid = tid >> 5;
    unsigned hl[8], lsum = 0;
#pragma unroll
    for (int k = 0; k < 8; k++) { hl[k] = __ldcg(&gh[tid * 8 + k]); lsum += hl[k]; }
    unsigned v = lsum;
#pragma unroll
    for (int s = 1; s < 32; s <<= 1) {
        unsigned o = __shfl_up_sync(0xffffffffu, v, s);
        if (lane >= s) v += o;
    }
    if (lane == 31) wS[wid] = v;
    __syncthreads();
    if (tid == 0) { unsigned run = 0; for (int w = 0; w < 16; w++) { run += wS[w]; wS[w] = run; } }
    __syncthreads();
    unsigned cum = (v - lsum) + (wid ? wS[wid - 1] : 0u);
#pragma unroll
    for (int k = 0; k < 8; k++) {
        unsigned hh = hl[k];
        if (hh && rank >= cum && rank < cum + hh) { *outBin = (unsigned)(tid * 8 + k); *outRem = rank - cum; }
        cum += hh;
    }
    __syncthreads();
}
__device__ void locateG4096(const unsigned* gh, unsigned rank, volatile unsigned* wS,
                            volatile unsigned* outBin, volatile unsigned* outRem) {
    int tid = threadIdx.x, lane = tid & 31, wid = tid >> 5;
    unsigned hl[16], lsum = 0;
#pragma unroll
    for (int k = 0; k < 16; k++) { hl[k] = __ldcg(&gh[tid * 16 + k]); lsum += hl[k]; }
    unsigned v = lsum;
#pragma unroll
    for (int s = 1; s < 32; s <<= 1) {
        unsigned o = __shfl_up_sync(0xffffffffu, v, s);
        if (lane >= s) v += o;
    }
    if (lane == 31) wS[wid] = v;
    __syncthreads();
    if (tid == 0) { unsigned run = 0; for (int w = 0; w < 8; w++) { run += wS[w]; wS[w] = run; } }
    __syncthreads();
    unsigned cum = (v - lsum) + (wid ? wS[wid - 1] : 0u);
#pragma unroll
    for (int k = 0; k < 16; k++) {
        unsigned h = hl[k];
        if (h && rank >= cum && rank < cum + h) { *outBin = (unsigned)(tid * 16 + k); *outRem = rank - cum; }
        cum += h;
    }
    __syncthreads();
}
__device__ void locateG256(const unsigned* gh, unsigned rank, volatile unsigned* wS,
                           volatile unsigned* outBin, volatile unsigned* outRem,
                           volatile unsigned* outCnt) {
    int tid = threadIdx.x, lane = tid & 31, wid = tid >> 5;
    unsigned h = (tid < 256) ? __ldcg(&gh[tid]) : 0u;
    unsigned v = h;
#pragma unroll
    for (int s = 1; s < 32; s <<= 1) {
        unsigned o = __shfl_up_sync(0xffffffffu, v, s);
        if (lane >= s) v += o;
    }
    if (lane == 31) wS[wid] = v;
    __syncthreads();
    if (tid == 0) { unsigned run = 0; for (int w = 0; w < 8; w++) { run += wS[w]; wS[w] = run; } }
    __syncthreads();
    unsigned cum = (v - h) + (wid ? wS[wid - 1] : 0u);
    if (h && rank >= cum && rank < cum + h) { *outBin = (unsigned)tid; *outRem = rank - cum; *outCnt = h; }
    __syncthreads();
}

// ================ K1 (512 thr): [pass1: 0-255] [norm+zero20: 256-319] [median: 320] [sort: 321] ================
__global__ __launch_bounds__(512) void prepPass1K(const float* __restrict__ t,
                                                  const float* __restrict__ emb,
                                                  const float* __restrict__ au) {
    __shared__ __align__(16) unsigned char sbuf[32768];
    __shared__ unsigned wS[16];
    __shared__ unsigned sA, sB_;
    __shared__ unsigned sAgg;
    __shared__ int sLast;
    int tid = threadIdx.x;
    int bid = blockIdx.x;

    if (bid < HB1) {
        float4* tsv4 = (float4*)sbuf;
        unsigned* hist = (unsigned*)(sbuf + 16384);
        const float* tss = (const float*)tsv4;
        for (int k = tid; k < 1024; k += 512) tsv4[k] = ((const float4*)t)[k];
        for (int x = tid; x < 4096; x += 512) hist[x] = 0u;
        if (tid == 0) sAgg = 0u;
        __syncthreads();

        unsigned zc = 0u;
        for (int i = bid; i < N; i += HB1) {
            float ti = tss[i];
            int v0 = (i + 1) >> 2;
            for (int v = v0 + tid; v < 1024; v += 512) {
                float4 w = tsv4[v];
                int jb = v << 2;
#pragma unroll
                for (int k = 0; k < 4; k++) {
                    float tj = (k == 0) ? w.x : (k == 1) ? w.y : (k == 2) ? w.z : w.w;
                    if (jb + k > i) {
                        unsigned b = __float_as_uint(fabsf(ti - tj));
                        if (b == 0u) zc++;
                        else atomicAdd(&hist[b >> 20], 1u);
                    }
                }
            }
        }
        __syncthreads();
        for (int x = tid; x < 4096; x += 512)
            if (hist[x]) atomicAdd(&g_hist1[x], hist[x]);
#pragma unroll
        for (int s = 16; s > 0; s >>= 1) zc += __shfl_xor_sync(0xffffffffu, zc, s);
        if ((tid & 31) == 0 && zc) atomicAdd(&sAgg, zc);
        __syncthreads();
        if (tid == 0 && sAgg) atomicAdd(&g_zeroPairs, sAgg);

        __threadfence();
        if (tid == 0) sLast = (atomicAdd(&g_doneCtr[0], 1u) == (unsigned)(HB1 - 1)) ? 1 : 0;
        __syncthreads();
        if (!sLast) return;

        unsigned z = __ldcg(&g_zeroPairs);
        unsigned mLo, mHi; float frac;
        rankMath(z, mLo, mHi, frac);
        locateG4096_512(g_hist1, mLo, wS, &sA, &sB_);
        if (tid == 0) {
            g_p1 = sA; g_r1 = sB_;
            g_mLo = mLo; g_mHi = mHi; g_frac = frac;
        }
        return;
    }

    if (bid < HB1 + 64) {
        int nb = bid - HB1;
        for (int x = tid; x < 16384; x += 512) g_hist20[nb * 16384 + x] = 0u;
        int warp = tid >> 5, lane = tid & 31;
#pragma unroll
        for (int q = 0; q < 4; q++) {
            int row = nb * 64 + warp * 4 + q;
            const float4* p = (const float4*)(emb + (size_t)row * D);
            float4 v = p[lane];
            float ss = v.x * v.x + v.y * v.y + v.z * v.z + v.w * v.w;
#pragma unroll
            for (int st = 16; st > 0; st >>= 1) ss += __shfl_xor_sync(0xffffffffu, ss, st);
            float inv = 1.0f / fmaxf(sqrtf(ss), 1e-12f);
            float o[4] = {v.x * inv, v.y * inv, v.z * inv, v.w * inv};
            __nv_bfloat16 h[4], l[4];
#pragma unroll
            for (int u = 0; u < 4; u++) {
                h[u] = __float2bfloat16(o[u]);
                l[u] = __float2bfloat16(o[u] - __bfloat162float(h[u]));
            }
            __nv_bfloat162* ph = (__nv_bfloat162*)(g_ahi + (size_t)row * D);
            __nv_bfloat162* pl = (__nv_bfloat162*)(g_alo + (size_t)row * D);
            ph[lane * 2]     = __nv_bfloat162{h[0], h[1]};
            ph[lane * 2 + 1] = __nv_bfloat162{h[2], h[3]};
            pl[lane * 2]     = __nv_bfloat162{l[0], l[1]};
            pl[lane * 2 + 1] = __nv_bfloat162{l[2], l[3]};
        }
        return;
    }

    if (bid == HB1 + 64) {
        unsigned* e = (unsigned*)sbuf;
        unsigned* h = (unsigned*)(sbuf + 16384);
        for (int i = tid; i < N; i += 512) e[i] = encodeF(au[i]);
        __syncthreads();
        float vals[2];
#pragma unroll 1
        for (int r = 0; r < 2; r++) {
            unsigned rank = 2047u + (unsigned)r;
            for (int x = tid; x < 4096; x += 512) h[x] = 0u;
            __syncthreads();
            for (int i = tid; i < N; i += 512) atomicAdd(&h[e[i] >> 20], 1u);
            __syncthreads();
            locateS4096_512(h, rank, wS, &sA, &sB_);
            unsigned b1 = sA, r1 = sB_;
            __syncthreads();
            for (int x = tid; x < 4096; x += 512) h[x] = 0u;
            __syncthreads();
            for (int i = tid; i < N; i += 512)
                if ((e[i] >> 20) == b1) atomicAdd(&h[(e[i] >> 8) & 0xFFFu], 1u);
            __syncthreads();
            locateS4096_512(h, r1, wS, &sA, &sB_);
            unsigned b2 = sA, r2 = sB_;
            unsigned pfx = (b1 << 12) | b2;
            __syncthreads();
            for (int x = tid; x < 4096; x += 512) h[x] = 0u;
            __syncthreads();
            for (int i = tid; i < N; i += 512)
                if ((e[i] >> 8) == pfx) atomicAdd(&h[e[i] & 0xFFu], 1u);
            __syncthreads();
            locateS4096_512(h, r2, wS, &sA, &sB_);
            unsigned b3 = sA;
            __syncthreads();
            vals[r] = decodeF((b1 << 20) | (b2 << 8) | b3);
        }
        float th = __fadd_rn(__fmul_rn(vals[0], 0.5f), __fmul_rn(vals[1], 0.5f));
        for (int i = tid; i < N; i += 512) g_low[i] = (au[i] < th) ? 1 : 0;
        return;
    }

    // ---- sort targets (bitonic, 512 threads) ----
    {
        float* s = (float*)sbuf;
        for (int i = tid; i < N; i += 512) s[i] = t[i];
        __syncthreads();
        for (int k = 2; k <= N; k <<= 1) {
            for (int j = k >> 1; j > 0; j >>= 1) {
                for (int idx = tid; idx < N; idx += 512) {
                    int p = idx ^ j;
                    if (p > idx) {
                        float a = s[idx], b2 = s[p];
                        bool up = ((idx & k) == 0);
                        bool sw = up ? (a > b2) : (a < b2);
                        if (sw) { s[idx] = b2; s[p] = a; }
                    }
                }
                __syncthreads();
            }
        }
        for (int i = tid; i < N; i += 512) g_tsorted[i] = s[i];
    }
}

// ================ K2: windowed pass 2 + (last block) selection -> g_actT ================
__global__ __launch_bounds__(256) void winPass2K() {
    __shared__ float ts[N];
    __shared__ unsigned wS[8];
    __shared__ unsigned sA, sB_, sC_, sD_;
    __shared__ int sLast;
    int tid = threadIdx.x;
    int warp = tid >> 5, lane = tid & 31;
    for (int i = tid; i < N; i += 256) ts[i] = g_tsorted[i];
    unsigned p1 = g_p1;
    unsigned loB = p1 << 20;
    unsigned hiB = ((p1 + 1u) << 20) - 1u;
    float loV = __uint_as_float(loB);
    float hiV = __uint_as_float(hiB);
    __syncthreads();

    int wg = blockIdx.x * 8 + warp;
    for (int i = wg; i < N; i += 1024) {
        float ti = ts[i];
        int jlo;
        if (loB == 0u) jlo = i + 1;
        else {
            int lo = i + 1, hi = N;
            while (lo < hi) {
                int m = (lo + hi) >> 1;
                if (ts[m] - ti >= loV) hi = m; else lo = m + 1;
            }
            jlo = lo;
        }
        int lo = jlo, hi = N;
        while (lo < hi) {
            int m = (lo + hi) >> 1;
            if (ts[m] - ti > hiV) hi = m; else lo = m + 1;
        }
        int jhiEx = lo;
        for (int j = jlo + lane; j < jhiEx; j += 32) {
            unsigned b = __float_as_uint(ts[j] - ti);
            if (b != 0u) {
                atomicAdd(&g_hist2[(b >> 8) & 0xFFFu], 1u);
                atomicAdd(&g_hist20[b & 0xFFFFFu], 1u);
            }
        }
        if (lane == 0 && jhiEx < N) {
            unsigned c = __float_as_uint(ts[jhiEx] - ti);
            atomicMax(&g_minCrossInv, ~c);
        }
    }

    // ---- last block: selection ----
    __threadfence();
    if (tid == 0) sLast = (atomicAdd(&g_doneCtr[1], 1u) == 127u) ? 1 : 0;
    __syncthreads();
    if (!sLast) return;

    unsigned r1 = g_r1;
    locateG4096(g_hist2, r1, wS, &sA, &sB_);
    unsigned bin2 = sA, rem2 = sB_;
    __syncthreads();
    locateG256(&g_hist20[bin2 << 8], rem2, wS, &sA, &sB_, &sC_);
    unsigned bin3 = sA, rem3 = sB_, cnt3 = sC_;
    __syncthreads();
    if (tid == 0) { sA = 0xFFFFFFFFu; sB_ = 0xFFFFFFFFu; sD_ = 0xFFFFFFFFu; }
    __syncthreads();
    if ((unsigned)tid > bin3 && __ldcg(&g_hist20[(bin2 << 8) + tid]) != 0u)
        atomicMin(&sA, (unsigned)tid);
#pragma unroll
    for (int k = 0; k < 16; k++) {
        unsigned idx = (unsigned)tid * 16u + (unsigned)k;
        if (idx > bin2 && __ldcg(&g_hist2[idx]) != 0u) atomicMin(&sB_, idx);
    }
    __syncthreads();
    unsigned nextA = sA, nbin2 = sB_;
    if (nbin2 != 0xFFFFFFFFu) {
        if (__ldcg(&g_hist20[(nbin2 << 8) + tid]) != 0u) atomicMin(&sD_, (unsigned)tid);
    }
    __syncthreads();
    if (tid == 0) {
        unsigned vlo = (p1 << 20) | (bin2 << 8) | bin3;
        unsigned mLo = g_mLo, mHi = g_mHi;
        float frac = g_frac;
        unsigned mAb = 0xFFFFFFFFu;
        if (nextA != 0xFFFFFFFFu) mAb = min(mAb, (p1 << 20) | (bin2 << 8) | nextA);
        if (nbin2 != 0xFFFFFFFFu && sD_ != 0xFFFFFFFFu)
            mAb = min(mAb, (p1 << 20) | (nbin2 << 8) | sD_);
        unsigned crossInv = __ldcg(&g_minCrossInv);
        if (crossInv) mAb = min(mAb, ~crossInv);
        bool same = (mHi == mLo) || (rem3 + 1u < cnt3);
        float flo = __uint_as_float(vlo);
        float fhi = same ? flo : __uint_as_float(mAb);
        g_actT = __fadd_rn(__fmul_rn(flo, 1.0f - frac), __fmul_rn(fhi, frac));
    }
}

// ================ K3: HMMA 64x128 tiles, 2 CTAs/SM; last block: final + resets ================
extern __shared__ unsigned char g_dyn[];
__global__ __launch_bounds__(256) void gemmHK(const float* __restrict__ t,
                                              float* __restrict__ out, int out_size) {
    __shared__ float tCol[128];
    __shared__ unsigned char lowCol[128];
    __shared__ unsigned sColMinI[2][128];
    __shared__ unsigned sColMax[2][128];
    __shared__ float fred[8];
    __shared__ unsigned ured[8];
    __shared__ int sLast;

    int tid = threadIdx.x;     // 256
    int warp = tid >> 5, lane = tid & 31;

    // tile mapping: for bj in 0..31, bi in 0..2bj+1
    int b = blockIdx.x;
    int bj = 0;
    while (b >= 2 * bj + 2) { b -= 2 * bj + 2; bj++; }
    int bi = b;
    int ri = bi * 64, rj = bj * 128;

    uint32_t sbase = smem_u32(g_dyn);

    // ---- load tiles: A 64 rows (hi/lo), B 128 rows (hi/lo) ----
    for (int i = tid; i < 1024; i += 256) {
        int row = i >> 4, ch = i & 15;
        unsigned off = (unsigned)row * TSTRIDE + (unsigned)ch * 16u;
        *(uint4*)(g_dyn + T_AHI + off) = ((const uint4*)(g_ahi + (size_t)(ri + row) * D))[ch];
        *(uint4*)(g_dyn + T_ALO + off) = ((const uint4*)(g_alo + (size_t)(ri + row) * D))[ch];
    }
    for (int i = tid; i < 2048; i += 256) {
        int row = i >> 4, ch = i & 15;
        unsigned off = (unsigned)row * TSTRIDE + (unsigned)ch * 16u;
        *(uint4*)(g_dyn + T_BHI + off) = ((const uint4*)(g_ahi + (size_t)(rj + row) * D))[ch];
        *(uint4*)(g_dyn + T_BLO + off) = ((const uint4*)(g_alo + (size_t)(rj + row) * D))[ch];
    }
    if (tid < 128) {
        tCol[tid] = t[rj + tid];
        lowCol[tid] = g_low[rj + tid];
    }
    __syncthreads();

    // warp grid: 2 (m) x 4 (n); warp tile 32x32
    int wr = warp >> 2, wc = warp & 3;
    int R = wr * 32, C = wc * 32;

    float acc[2][4][4];
#pragma unroll
    for (int mt = 0; mt < 2; mt++)
#pragma unroll
        for (int nt = 0; nt < 4; nt++)
#pragma unroll
            for (int q = 0; q < 4; q++) acc[mt][nt][q] = 0.0f;

    unsigned aRow = (unsigned)((lane & 7) + ((lane >> 3) & 1) * 8);
    unsigned aByte = (unsigned)((lane >> 4) * 16);
    unsigned bRow = (unsigned)(((lane >> 4) * 8) + (lane & 7));
    unsigned bByte = (unsigned)(((lane >> 3) & 1) * 16);

#pragma unroll 1
    for (int split = 0; split < 3; split++) {
        unsigned At = sbase + ((split == 2) ? T_ALO : T_AHI);
        unsigned Bt = sbase + ((split == 1) ? T_BLO : T_BHI);
#pragma unroll
        for (int kb = 0; kb < 8; kb++) {
            unsigned kByte = (unsigned)kb * 32u;
            unsigned a[2][4];
#pragma unroll
            for (int mt = 0; mt < 2; mt++) {
                unsigned addr = At + (unsigned)(R + mt * 16 + aRow) * TSTRIDE + kByte + aByte;
                ldsm4(a[mt], addr);
            }
#pragma unroll
            for (int ntp = 0; ntp < 2; ntp++) {
                unsigned bm[4];
                unsigned addr = Bt + (unsigned)(C + ntp * 16 + bRow) * TSTRIDE + kByte + bByte;
                ldsm4(bm, addr);
                mma16816(acc[0][ntp * 2],     a[0], bm[0], bm[1]);
                mma16816(acc[0][ntp * 2 + 1], a[0], bm[2], bm[3]);
                mma16816(acc[1][ntp * 2],     a[1], bm[0], bm[1]);
                mma16816(acc[1][ntp * 2 + 1], a[1], bm[2], bm[3]);
            }
        }
    }

    // ---- masked epilogue ----
    float actT = g_actT;
    float pMin[4], nMax[4];
#pragma unroll
    for (int u = 0; u < 4; u++) { pMin[u] = 3.402823466e38f; nMax[u] = -3.402823466e38f; }
    unsigned cMinI[4][2], cMax[4][2];
#pragma unroll
    for (int nt = 0; nt < 4; nt++) { cMinI[nt][0] = cMinI[nt][1] = 0u; cMax[nt][0] = cMax[nt][1] = 0u; }

#pragma unroll
    for (int mt = 0; mt < 2; mt++) {
        int rA = ri + R + mt * 16 + (lane >> 2);
        int rB = rA + 8;
        float tA = t[rA], tB = t[rB];
        int lA = g_low[rA], lB = g_low[rB];
#pragma unroll
        for (int nt = 0; nt < 4; nt++) {
            int lc0 = C + nt * 8 + (lane & 3) * 2;
#pragma unroll
            for (int s = 0; s < 2; s++) {
                int lc = lc0 + s;
                int gcol = rj + lc;
                float tc = tCol[lc];
                int lj = lowCol[lc];
                {
                    float dv = acc[mt][nt][s];
                    float ad = fabsf(tA - tc);
                    if (ad < actT) {
                        bool neq = rA != gcol;
                        if (lj) { if (neq) pMin[mt * 2] = fminf(pMin[mt * 2], dv); }
                        else nMax[mt * 2] = fmaxf(nMax[mt * 2], dv);
                        if (lA && neq) cMinI[nt][s] = max(cMinI[nt][s], ~encodeF(dv));
                        if (!lA) cMax[nt][s] = max(cMax[nt][s], encodeF(dv));
                    }
                }
                {
                    float dv = acc[mt][nt][2 + s];
                    float ad = fabsf(tB - tc);
                    if (ad < actT) {
                        bool neq = rB != gcol;
                        if (lj) { if (neq) pMin[mt * 2 + 1] = fminf(pMin[mt * 2 + 1], dv); }
                        else nMax[mt * 2 + 1] = fmaxf(nMax[mt * 2 + 1], dv);
                        if (lB && neq) cMinI[nt][s] = max(cMinI[nt][s], ~encodeF(dv));
                        if (!lB) cMax[nt][s] = max(cMax[nt][s], encodeF(dv));
                    }
                }
            }
        }
    }
    // row side: quad reduce
#pragma unroll
    for (int s = 1; s < 4; s <<= 1) {
#pragma unroll
        for (int u = 0; u < 4; u++) {
            pMin[u] = fminf(pMin[u], __shfl_xor_sync(0xffffffffu, pMin[u], s));
            nMax[u] = fmaxf(nMax[u], __shfl_xor_sync(0xffffffffu, nMax[u], s));
        }
    }
    if ((lane & 3) == 0) {
#pragma unroll
        for (int mt = 0; mt < 2; mt++) {
            int rA = ri + R + mt * 16 + (lane >> 2);
            int rB = rA + 8;
            if (pMin[mt * 2] < 3.0e38f) atomicMax(&g_rowMinInv[rA], ~encodeF(pMin[mt * 2]));
            if (nMax[mt * 2] > -3.0e38f) atomicMax(&g_rowMaxNeg[rA], encodeF(nMax[mt * 2]));
            if (pMin[mt * 2 + 1] < 3.0e38f) atomicMax(&g_rowMinInv[rB], ~encodeF(pMin[mt * 2 + 1]));
            if (nMax[mt * 2 + 1] > -3.0e38f) atomicMax(&g_rowMaxNeg[rB], encodeF(nMax[mt * 2 + 1]));
        }
    }
    // col side: reduce across lanes sharing cols (bits 2-4)
#pragma unroll
    for (int s = 4; s < 32; s <<= 1) {
#pragma unroll
        for (int nt = 0; nt < 4; nt++)
#pragma unroll
            for (int q = 0; q < 2; q++) {
                cMinI[nt][q] = max(cMinI[nt][q], __shfl_xor_sync(0xffffffffu, cMinI[nt][q], s));
                cMax[nt][q] = max(cMax[nt][q], __shfl_xor_sync(0xffffffffu, cMax[nt][q], s));
            }
    }
    if (lane < 4) {
#pragma unroll
        for (int nt = 0; nt < 4; nt++)
#pragma unroll
            for (int q = 0; q < 2; q++) {
                int lc = C + nt * 8 + lane * 2 + q;
                sColMinI[wr][lc] = cMinI[nt][q];
                sColMax[wr][lc] = cMax[nt][q];
            }
    }
    __syncthreads();
    if (tid < 128) {
        unsigned vI = max(sColMinI[0][tid], sColMinI[1][tid]);
        unsigned vX = max(sColMax[0][tid], sColMax[1][tid]);
        if (vI) atomicMax(&g_rowMinInv[rj + tid], vI);
        if (vX) atomicMax(&g_rowMaxNeg[rj + tid], vX);
    }

    // ---- last block: final loss + resets ----
    __threadfence();
    if (tid == 0) sLast = (atomicAdd(&g_doneCtr[2], 1u) == (unsigned)(GB2 - 1)) ? 1 : 0;
    __syncthreads();
    if (!sLast) return;

    float sum = 0.0f;
    unsigned cnt = 0u;
    for (int i = tid; i < N; i += 256) {
        if (g_low[i] == 0) continue;
        unsigned rInv = __ldcg(&g_rowMinInv[i]);
        if (rInv == 0u) continue;
        unsigned en = __ldcg(&g_rowMaxNeg[i]);
        if (en == 0u) continue;
        float minDot = decodeF(~rInv);
        float maxDot = decodeF(en);
        float hp = sqrtf(fmaxf(2.0f - 2.0f * minDot, 1e-12f));
        float hn = sqrtf(fmaxf(2.0f - 2.0f * maxDot, 1e-12f));
        float tl = hp - hn + 0.5f;
        if (tl < 0.0f) tl = 0.0f;
        sum += tl;
        cnt++;
    }
#pragma unroll
    for (int s = 16; s > 0; s >>= 1) {
        sum += __shfl_down_sync(0xffffffffu, sum, s);
        cnt += __shfl_down_sync(0xffffffffu, cnt, s);
    }
    if (lane == 0) { fred[warp] = sum; ured[warp] = cnt; }
    __syncthreads();
    if (tid == 0) {
        float s2 = 0.0f;
        unsigned c2 = 0u;
#pragma unroll
        for (int w = 0; w < 8; w++) { s2 += fred[w]; c2 += ured[w]; }
        out[0] = s2 / (float)(c2 > 0u ? c2 : 1u);
    }
    for (int i = tid; i < out_size; i += 256)
        if (i > 0) out[i] = 0.0f;

    for (int x = tid; x < 4096; x += 256) {
        g_hist1[x] = 0u;
        g_hist2[x] = 0u;
        g_rowMinInv[x] = 0u;
        g_rowMaxNeg[x] = 0u;
    }
    if (tid < 4) g_doneCtr[tid] = 0u;
    if (tid == 0) {
        g_zeroPairs = 0u;
        g_minCrossInv = 0u;
    }
}

// ---------------- launch ----------------
extern "C" void kernel_launch(void* const* d_in, const int* in_sizes, int n_in,
                              void* d_out, int out_size) {
    const float* emb = (const float*)d_in[0];
    const float* tg = (const float*)d_in[1];
    const float* au = (const float*)d_in[2];
    float* out = (float*)d_out;

    cudaFuncSetAttribute(gemmHK, cudaFuncAttributeMaxDynamicSharedMemorySize, DYN_SMEM);

    prepPass1K<<<HB1 + 64 + 2, 512>>>(tg, emb, au);     // 1
    winPass2K<<<128, 256>>>();                          // 2
    gemmHK<<<GB2, 256, DYN_SMEM>>>(tg, out, out_size);  // 3
}